// round 12
// baseline (speedup 1.0000x reference)
#include <cuda_runtime.h>
#include <stdint.h>

// Algebraic feature expansion:
//   out[:, 0:16]    = x
//   out[:, 16:136]  = pair products  x[a]*x[b]   (lex order)
//   out[:, 136:696] = triple products x[a]*x[b]*x[c] (lex order)
// B=262144 rows, 696 out cols. HBM-store-bound; v10 runs at ~7.3 TB/s eff.
//
// v12: v10's exact per-output code (constant table, 12 LDS + 8 FMUL per
// chunk, full 16-row unroll, __stcs) but TWO tiles per block (BLK=384,
// grid=8192): threads [0,174) compute tile A (rows 0-15), [192,366) tile B
// (rows 16-31); both tile loads issue up front under ONE __syncthreads.
// Same occupancy (4 blk/SM * 384 = 1536 thr/SM == v10's 8*192); half the
// launches and per-tile preamble.

#define NC     16
#define NPAIR  120
#define OUTC   696
#define Q4     174          // OUTC / 4
#define RTILE  16           // rows per tile
#define TILES  2            // tiles per block
#define ROWS   (RTILE * TILES)
#define PAD    20           // floats per cached row (16 data + 1.0 dummy + align)
#define BLK    384          // 12 warps; [0,174) tile A, [192,366) tile B

// ---- Compile-time packed index table: a | b<<8 | c<<16 (16 = dummy -> 1.0) ----
struct Tab { unsigned v[OUTC]; };

static constexpr Tab make_tab() {
    Tab t{};
    int col = 0;
    for (int a = 0; a < NC; a++)
        t.v[col++] = (unsigned)a | (16u << 8) | (16u << 16);
    for (int a = 0; a < NC; a++)
        for (int b = a + 1; b < NC; b++)
            t.v[col++] = (unsigned)a | ((unsigned)b << 8) | (16u << 16);
    for (int a = 0; a < NC; a++)
        for (int b = a + 1; b < NC; b++)
            for (int c = b + 1; c < NC; c++)
                t.v[col++] = (unsigned)a | ((unsigned)b << 8) | ((unsigned)c << 16);
    return t;
}

__constant__ Tab ctab = make_tab();

__global__ __launch_bounds__(BLK) void algebraic_expand_kernel(
    const float* __restrict__ x,
    float4* __restrict__ out4,
    int nrows)
{
    __shared__ __align__(16) float xs[ROWS][PAD];

    const int t    = threadIdx.x;
    const int row0 = blockIdx.x * ROWS;          // first row of tile A

    // ---- Kick off BOTH tile loads first (LDG in flight during decode) ----
    float4 ld;
    const bool loader = (t < ROWS * NC / 4);     // 128 loader threads -> 32 rows
    const int lr = t >> 2;                       // row within block (0..31)
    const int lc = (t & 3) << 2;
    const bool do_ld = loader && (row0 + lr < nrows);
    if (do_ld)
        ld = reinterpret_cast<const float4*>(x + (size_t)row0 * NC)[t];

    // ---- Role: which tile, which chunk ----
    const int half  = (t >= 192) ? 1 : 0;        // tile B for threads >= 192
    const int ct    = t - half * 192;            // chunk id within tile
    const bool active = (ct < Q4);
    const int rbase = half * RTILE;              // smem row base for this tile

    // ---- Decode this thread's fixed chunk from __constant__ (overlaps LDG) ----
    const float* base = &xs[rbase][0];
    const float *p0 = base, *p1 = base, *p2 = base, *p3 = base,
                *p4 = base, *p5 = base, *p6 = base, *p7 = base,
                *p8 = base, *p9 = base, *pa = base, *pb = base;
    if (active) {
        const uint4 pk = reinterpret_cast<const uint4*>(ctab.v)[ct];
        p0 = base + ( pk.x        & 255u);
        p1 = base + ((pk.x >>  8) & 255u);
        p2 = base + ( pk.x >> 16        );
        p3 = base + ( pk.y        & 255u);
        p4 = base + ((pk.y >>  8) & 255u);
        p5 = base + ( pk.y >> 16        );
        p6 = base + ( pk.z        & 255u);
        p7 = base + ((pk.z >>  8) & 255u);
        p8 = base + ( pk.z >> 16        );
        p9 = base + ( pk.w        & 255u);
        pa = base + ((pk.w >>  8) & 255u);
        pb = base + ( pk.w >> 16        );
    }

    // ---- Stage both tiles ----
    if (do_ld)
        *reinterpret_cast<float4*>(&xs[lr][lc]) = ld;
    if (t < ROWS) xs[t][16] = 1.0f;              // dummy operand, all 32 rows
    __syncthreads();

    if (!active) return;

    const int trow0 = row0 + rbase;              // first global row of MY tile
    float4* ob = out4 + (size_t)trow0 * Q4 + ct;

    if (trow0 + RTILE <= nrows) {
        // fast path: full tile, all offsets compile-time immediates
        #pragma unroll
        for (int r = 0; r < RTILE; r++) {
            const int o = r * PAD;
            float4 v;
            v.x = p0[o] * p1[o] * p2[o];
            v.y = p3[o] * p4[o] * p5[o];
            v.z = p6[o] * p7[o] * p8[o];
            v.w = p9[o] * pa[o] * pb[o];
            __stcs(&ob[(size_t)r * Q4], v);
        }
    } else {
        const int rem = nrows - trow0;
        for (int r = 0; r < rem; r++) {
            const int o = r * PAD;
            float4 v;
            v.x = p0[o] * p1[o] * p2[o];
            v.y = p3[o] * p4[o] * p5[o];
            v.z = p6[o] * p7[o] * p8[o];
            v.w = p9[o] * pa[o] * pb[o];
            __stcs(&ob[(size_t)r * Q4], v);
        }
    }
}

extern "C" void kernel_launch(void* const* d_in, const int* in_sizes, int n_in,
                              void* d_out, int out_size)
{
    const float* x = (const float*)d_in[0];
    const int nrows = in_sizes[0] / NC;

    const int nblocks = (nrows + ROWS - 1) / ROWS;   // 8192 for B=262144
    algebraic_expand_kernel<<<nblocks, BLK>>>(x, (float4*)d_out, nrows);
}

// round 13
// speedup vs baseline: 1.1325x; 1.1325x over previous
#include <cuda_runtime.h>
#include <stdint.h>

// Algebraic feature expansion:
//   out[:, 0:16]    = x
//   out[:, 16:136]  = pair products  x[a]*x[b]   (lex order)
//   out[:, 136:696] = triple products x[a]*x[b]*x[c] (lex order)
// B=262144 rows, 696 out cols. HBM-store-bound (~730 MB out).
//
// v13: v10 (one tile per block, constant table, 12 LDS + 8 FMUL per chunk,
// __stcs) with RTILE halved to 8 -> grid = 32768. R9/R10/R12 established
// that, at fixed occupancy, more smaller independent blocks win (scheduler
// interleaves load phases with other blocks' store bursts). This extends
// that direction: sync domain still 6 warps, block turnover doubles.

#define NC    16
#define NPAIR 120
#define OUTC  696
#define Q4    174          // OUTC / 4
#define RTILE 8            // rows per tile (262144/8 = 32768 blocks)
#define PAD   20           // floats per cached row (16 data + 1.0 dummy + align)
#define BLK   192          // 6 warps; threads [0,174) compute, [0,32) load

// ---- Compile-time packed index table: a | b<<8 | c<<16 (16 = dummy -> 1.0) ----
struct Tab { unsigned v[OUTC]; };

static constexpr Tab make_tab() {
    Tab t{};
    int col = 0;
    for (int a = 0; a < NC; a++)
        t.v[col++] = (unsigned)a | (16u << 8) | (16u << 16);
    for (int a = 0; a < NC; a++)
        for (int b = a + 1; b < NC; b++)
            t.v[col++] = (unsigned)a | ((unsigned)b << 8) | (16u << 16);
    for (int a = 0; a < NC; a++)
        for (int b = a + 1; b < NC; b++)
            for (int c = b + 1; c < NC; c++)
                t.v[col++] = (unsigned)a | ((unsigned)b << 8) | ((unsigned)c << 16);
    return t;
}

__constant__ Tab ctab = make_tab();

__global__ __launch_bounds__(BLK) void algebraic_expand_kernel(
    const float* __restrict__ x,
    float4* __restrict__ out4,
    int nrows)
{
    __shared__ __align__(16) float xs[RTILE][PAD];

    const int t    = threadIdx.x;
    const int row0 = blockIdx.x * RTILE;

    // ---- Kick off the tile load first (LDG in flight during decode) ----
    float4 ld;
    const bool loader = (t < RTILE * NC / 4);     // 32 loader threads
    const int lr = t >> 2;
    const int lc = (t & 3) << 2;
    const bool do_ld = loader && (row0 + lr < nrows);
    if (do_ld)
        ld = reinterpret_cast<const float4*>(x + (size_t)row0 * NC)[t];

    // ---- Decode this thread's fixed chunk from __constant__ (overlaps LDG) ----
    const bool active = (t < Q4);
    const float* base = &xs[0][0];
    const float *p0 = base, *p1 = base, *p2 = base, *p3 = base,
                *p4 = base, *p5 = base, *p6 = base, *p7 = base,
                *p8 = base, *p9 = base, *pa = base, *pb = base;
    if (active) {
        const uint4 pk = reinterpret_cast<const uint4*>(ctab.v)[t];
        p0 = base + ( pk.x        & 255u);
        p1 = base + ((pk.x >>  8) & 255u);
        p2 = base + ( pk.x >> 16        );
        p3 = base + ( pk.y        & 255u);
        p4 = base + ((pk.y >>  8) & 255u);
        p5 = base + ( pk.y >> 16        );
        p6 = base + ( pk.z        & 255u);
        p7 = base + ((pk.z >>  8) & 255u);
        p8 = base + ( pk.z >> 16        );
        p9 = base + ( pk.w        & 255u);
        pa = base + ((pk.w >>  8) & 255u);
        pb = base + ( pk.w >> 16        );
    }

    // ---- Stage the tile ----
    if (do_ld)
        *reinterpret_cast<float4*>(&xs[lr][lc]) = ld;
    if (t < RTILE) xs[t][16] = 1.0f;   // dummy operand
    __syncthreads();

    if (!active) return;

    float4* ob = out4 + (size_t)row0 * Q4 + t;

    if (row0 + RTILE <= nrows) {
        // fast path: full tile, all offsets compile-time immediates
        #pragma unroll
        for (int r = 0; r < RTILE; r++) {
            const int o = r * PAD;
            float4 v;
            v.x = p0[o] * p1[o] * p2[o];
            v.y = p3[o] * p4[o] * p5[o];
            v.z = p6[o] * p7[o] * p8[o];
            v.w = p9[o] * pa[o] * pb[o];
            __stcs(&ob[(size_t)r * Q4], v);
        }
    } else {
        const int rem = nrows - row0;
        for (int r = 0; r < rem; r++) {
            const int o = r * PAD;
            float4 v;
            v.x = p0[o] * p1[o] * p2[o];
            v.y = p3[o] * p4[o] * p5[o];
            v.z = p6[o] * p7[o] * p8[o];
            v.w = p9[o] * pa[o] * pb[o];
            __stcs(&ob[(size_t)r * Q4], v);
        }
    }
}

extern "C" void kernel_launch(void* const* d_in, const int* in_sizes, int n_in,
                              void* d_out, int out_size)
{
    const float* x = (const float*)d_in[0];
    const int nrows = in_sizes[0] / NC;

    const int nblocks = (nrows + RTILE - 1) / RTILE;   // 32768 for B=262144
    algebraic_expand_kernel<<<nblocks, BLK>>>(x, (float4*)d_out, nrows);
}